// round 15
// baseline (speedup 1.0000x reference)
#include <cuda_runtime.h>
#include <cuda_bf16.h>
#include <math.h>
#include <stdint.h>

#define BSZ 8
#define PP  16384
#define NPT (BSZ*PP)       // 131072
#define TOKD 768
#define MT  128
#define KNN 16
#define IHD 256
#define NGRP (BSZ*MT)      // 1024 centroids
#define NGATH (NGRP*KNN)   // 16384 gathered rows

typedef __nv_bfloat16 bf16;

// ---------------- scratch (device globals) ----------------
__device__ bf16  g_znh[(size_t)NPT*256];
__device__ bf16  g_znl[(size_t)NPT*256];
__device__ bf16  g_h2h[(size_t)NPT*512];
__device__ bf16  g_h2l[(size_t)NPT*512];
__device__ bf16  g_h3h[(size_t)NPT*768];
__device__ bf16  g_h3l[(size_t)NPT*768];
__device__ float g_imp[NPT];
__device__ float4 g_c4[NPT];
__device__ int   g_sel[NGRP];
__device__ int   g_knn[NGATH];
__device__ bf16  g_ph[(size_t)NGRP*768], g_pl[(size_t)NGRP*768];
__device__ bf16  g_t1h[(size_t)NGRP*768], g_t1l[(size_t)NGRP*768];
// transposed split weights: layout [Kout][Kpad]
__device__ bf16  g_w2h[512*256],  g_w2l[512*256];
__device__ bf16  g_w3h[768*512],  g_w3l[768*512];
__device__ bf16  g_w4h[768*768],  g_w4l[768*768];
__device__ bf16  g_wih[256*768],  g_wil[256*768];   // W4i = w4 @ iw1[0:768]
__device__ float g_b2[256];                          // ib1 + b4 @ iw1[0:768]
__device__ bf16  g_iw2h[256*256], g_iw2l[256*256];
__device__ bf16  g_nw1h[768*768], g_nw1l[768*768];
__device__ bf16  g_nw2h[768*768], g_nw2l[768*768];

// ---------------- PTX helpers (baseline ISA only) ----------------
__device__ __forceinline__ uint32_t smem_u32(const void* p) {
    uint32_t a;
    asm("{ .reg .u64 t; cvta.to.shared.u64 t, %1; cvt.u32.u64 %0, t; }"
        : "=r"(a) : "l"(p));
    return a;
}
__device__ __forceinline__ void cp16(uint32_t dst, const void* src) {
    asm volatile("cp.async.cg.shared.global [%0], [%1], 16;"
        :: "r"(dst), "l"(src) : "memory");
}
__device__ __forceinline__ void cp_commit() {
    asm volatile("cp.async.commit_group;" ::: "memory");
}
__device__ __forceinline__ void cp_wait1() {
    asm volatile("cp.async.wait_group 1;" ::: "memory");
}
__device__ __forceinline__ void cp_wait0() {
    asm volatile("cp.async.wait_group 0;" ::: "memory");
}
__device__ __forceinline__ void ldsm4(uint32_t* r, uint32_t a) {
    asm volatile("ldmatrix.sync.aligned.m8n8.x4.shared.b16 {%0,%1,%2,%3}, [%4];"
        : "=r"(r[0]), "=r"(r[1]), "=r"(r[2]), "=r"(r[3]) : "r"(a));
}
__device__ __forceinline__ void mma16816(float* d, const uint32_t* a, const uint32_t* b) {
    asm volatile("mma.sync.aligned.m16n8k16.row.col.f32.bf16.bf16.f32 "
        "{%0,%1,%2,%3}, {%4,%5,%6,%7}, {%8,%9}, {%0,%1,%2,%3};"
        : "+f"(d[0]), "+f"(d[1]), "+f"(d[2]), "+f"(d[3])
        : "r"(a[0]), "r"(a[1]), "r"(a[2]), "r"(a[3]), "r"(b[0]), "r"(b[1]));
}
__device__ __forceinline__ void split_bf16(float v, bf16& h, bf16& l) {
    h = __float2bfloat16(v);
    l = __float2bfloat16(v - __bfloat162float(h));
}
__device__ __forceinline__ uint32_t pack2(bf16 a, bf16 b) {
    __nv_bfloat162 t; t.x = a; t.y = b;
    return *(uint32_t*)&t;
}

// ---------------- mma.sync split-bf16 GEMM, 128xNT CTA tile ----------------
#define TILE_A   16384          // 128x64 bf16 tile (A hi or lo)
#define RS 264                  // stash row stride (floats)
#define STAGE256  (2*TILE_A + 2*(256*128))      // 98304
#define EXTRA_OFF (1024 + 2*STAGE256)           // 197632
#define MMA_SMEM (EXTRA_OFF + 10240)            // 207872
#define MMA_SMEM128 (1024 + 2*(2*TILE_A + 2*(128*128)))  // 132096

extern __shared__ char smem_dyn_c[];

// cp.async one tile (nri*256 16B-chunks) with SW128 swizzle; optional row indirection
__device__ __forceinline__ void tile_cp(const bf16* __restrict__ src, int rowBase,
                                        int Kstride, int kc, uint32_t dstBase,
                                        int tid, int nri, const int* __restrict__ rowIdx)
{
#pragma unroll
    for (int j = 0; j < 8; j++) {
        if (j >= nri) break;
        int i = tid + j * 256;
        int r = i >> 3, ck = i & 7;
        int gr = rowIdx ? rowIdx[rowBase + r] : (rowBase + r);
        const bf16* s = src + (size_t)gr * Kstride + kc * 64 + ck * 8;
        uint32_t off = (uint32_t)(r * 128 + ((ck * 16) ^ ((r & 7) << 4)));
        cp16(dstBase + off, s);
    }
}

// generate h1 chunk (128 rows x 64 cols starting at kc*64) straight into smem tiles
__device__ __forceinline__ void gen_h1_tile(char* smem, char* dstAh, char* dstAl,
                                            int kc, int tid)
{
    const float* w1s = (const float*)(smem + EXTRA_OFF);
    const float* b1s = (const float*)(smem + EXTRA_OFF + 6144);
    const float* fs  = (const float*)(smem + EXTRA_OFF + 7168);
#pragma unroll
    for (int j = 0; j < 4; j++) {
        int i = tid + j * 256;
        int r = i >> 3, ck = i & 7;
        int c0 = kc * 64 + ck * 8;
        const float* fr = &fs[r * 6];
        float f0 = fr[0], f1 = fr[1], f2 = fr[2], f3 = fr[3], f4 = fr[4], f5 = fr[5];
        uint32_t hp[4], lp[4];
#pragma unroll
        for (int m = 0; m < 4; m++) {
            int ca = c0 + m * 2, cb = c0 + m * 2 + 1;
            float va = b1s[ca] + f0 * w1s[ca] + f1 * w1s[256 + ca] + f2 * w1s[512 + ca]
                     + f3 * w1s[768 + ca] + f4 * w1s[1024 + ca] + f5 * w1s[1280 + ca];
            float vb = b1s[cb] + f0 * w1s[cb] + f1 * w1s[256 + cb] + f2 * w1s[512 + cb]
                     + f3 * w1s[768 + cb] + f4 * w1s[1024 + cb] + f5 * w1s[1280 + cb];
            va = fmaxf(va, 0.f); vb = fmaxf(vb, 0.f);
            bf16 ha, la, hb, lb;
            split_bf16(va, ha, la); split_bf16(vb, hb, lb);
            hp[m] = pack2(ha, hb); lp[m] = pack2(la, lb);
        }
        uint32_t off = (uint32_t)(r * 128 + ((ck * 16) ^ ((r & 7) << 4)));
        *(uint4*)(dstAh + off) = make_uint4(hp[0], hp[1], hp[2], hp[3]);
        *(uint4*)(dstAl + off) = make_uint4(lp[0], lp[1], lp[2], lp[3]);
    }
}

// mode: 0 = normal (Cf/Ch/Cl out), 1 = coords-term + relu + LN + split (Ch/Cl = zn),
//       2 = relu + dot iw3 (impOut), 3 = 16-row max-pool + split (Ch/Cl = pooled)
template<int NT>
__global__ __launch_bounds__(256)
void mma_gemm(const bf16* __restrict__ Ah, const bf16* __restrict__ Al,
              const bf16* __restrict__ Bh, const bf16* __restrict__ Bl,
              const float* __restrict__ bias,
              float* __restrict__ Cf, bf16* __restrict__ Ch, bf16* __restrict__ Cl,
              int strideC, int Kpad, int Kout, int doRelu, int mode,
              const float* __restrict__ ln_g, const float* __restrict__ ln_b,
              const float* __restrict__ iw3, const float* __restrict__ ib3,
              float* __restrict__ impOut,
              const int* __restrict__ rowIdx, const float* __restrict__ coords,
              const float* __restrict__ iw1full,
              const float* __restrict__ gAf, const float* __restrict__ gAw,
              const float* __restrict__ gAb)
{
    constexpr int TILE_B  = NT * 128;
    constexpr int STAGE   = 2*TILE_A + 2*TILE_B;
    constexpr int NB      = NT / 64;
    constexpr int NF      = NT / 32;
    constexpr int BTILES  = NT / 32;

    char* smem = smem_dyn_c;
    const uint32_t sbase = smem_u32(smem);
    float* Sb = (float*)smem;
    const uint32_t tiles0 = sbase + 1024;
    char* tiles0p = smem + 1024;
    const int tid  = threadIdx.x;
    const int wid  = tid >> 5;
    const int lane = tid & 31;
    const int wm   = wid >> 2;
    const int wn   = wid & 3;
    const int bRow = blockIdx.y * 128;
    const int bCol = blockIdx.x * NT;

    if (tid < NT) Sb[tid] = bias[bCol + tid];

    if (NT == 256 && gAw) {
        float* w1s = (float*)(smem + EXTRA_OFF);
        float* b1s = (float*)(smem + EXTRA_OFF + 6144);
        float* fs  = (float*)(smem + EXTRA_OFF + 7168);
        for (int i = tid; i < 1536; i += 256) w1s[i] = gAw[i];
        b1s[tid] = gAb[tid];
        for (int i = tid; i < 768; i += 256) {
            int r = i / 6, k = i - r * 6;
            fs[i] = gAf[(size_t)(bRow + r) * 6 + k];
        }
        __syncthreads();
    }

    uint32_t aOff[4], bOff[NB];
    {
        int khalfA = ((lane >> 4) & 1) * 16;
#pragma unroll
        for (int mf = 0; mf < 4; mf++) {
            int r = wm * 64 + mf * 16 + ((lane >> 3) & 1) * 8 + (lane & 7);
            aOff[mf] = (uint32_t)(r * 128 + (khalfA ^ ((r & 7) << 4)));
        }
        int khalfB = ((lane >> 3) & 1) * 16;
#pragma unroll
        for (int nb = 0; nb < NB; nb++) {
            int r = wn * (NT/4) + nb * 16 + ((lane >> 4) & 1) * 8 + (lane & 7);
            bOff[nb] = (uint32_t)(r * 128 + (khalfB ^ ((r & 7) << 4)));
        }
    }

    float acc[4][NF][4];
#pragma unroll
    for (int i = 0; i < 4; i++)
#pragma unroll
        for (int j = 0; j < NF; j++)
#pragma unroll
            for (int c = 0; c < 4; c++) acc[i][j][c] = 0.f;

    const int T = Kpad / 64;

    // prologue: chunk 0 -> buffer 0, two commit groups:
    //   G1 = {Ah, Bh} (phase-1 operands), G2 = {Al, Bl}
    if (NT == 256 && gAw) {
        gen_h1_tile(smem, tiles0p, tiles0p + TILE_A, 0, tid);
        tile_cp(Bh, bCol, Kpad, 0, tiles0 + 2*TILE_A, tid, BTILES, nullptr);
        cp_commit();
        tile_cp(Bl, bCol, Kpad, 0, tiles0 + 2*TILE_A + TILE_B, tid, BTILES, nullptr);
        cp_commit();
    } else {
        tile_cp(Ah, bRow, Kpad, 0, tiles0,            tid, 4, rowIdx);
        tile_cp(Bh, bCol, Kpad, 0, tiles0 + 2*TILE_A, tid, BTILES, nullptr);
        cp_commit();
        tile_cp(Al, bRow, Kpad, 0, tiles0 + TILE_A,            tid, 4, rowIdx);
        tile_cp(Bl, bCol, Kpad, 0, tiles0 + 2*TILE_A + TILE_B, tid, BTILES, nullptr);
        cp_commit();
    }

    // split-group 1.5-deep pipeline:
    //  A) wait<=1 (G1(t) done; G2(t) may fly) -> sync
    //  B) issue G1(t+1)   [buffer t+1 last read in chunk t-1, ordered by A's sync]
    //  C) phase1(t): Ah x Bh
    //  D) wait (G2(t) done) -> sync
    //  E) issue G2(t+1)
    //  F) phase2(t): Al x Bh + Ah x Bl
    for (int t = 0; t < T; t++) {
        cp_wait1();
        __syncthreads();
        const uint32_t st  = tiles0 + (t & 1) * STAGE;
        const uint32_t tAh = st, tAl = st + TILE_A;
        const uint32_t tBh = st + 2*TILE_A, tBl = st + 2*TILE_A + TILE_B;

        if (t + 1 < T) {
            uint32_t sn = tiles0 + ((t + 1) & 1) * STAGE;
            char*    sp = tiles0p + ((t + 1) & 1) * STAGE;
            if (NT == 256 && gAw) {
                gen_h1_tile(smem, sp, sp + TILE_A, t + 1, tid);
            } else {
                tile_cp(Ah, bRow, Kpad, t + 1, sn, tid, 4, rowIdx);
            }
            tile_cp(Bh, bCol, Kpad, t + 1, sn + 2*TILE_A, tid, BTILES, nullptr);
            cp_commit();
        }

        // phase 1: Ah x Bh
#pragma unroll
        for (int ks = 0; ks < 4; ks++) {
            const uint32_t kx = (uint32_t)(ks << 5);
            uint32_t aa[4][4], bb[NB][4];
#pragma unroll
            for (int mf = 0; mf < 4; mf++) ldsm4(aa[mf], tAh + (aOff[mf] ^ kx));
#pragma unroll
            for (int nb = 0; nb < NB; nb++) ldsm4(bb[nb], tBh + (bOff[nb] ^ kx));
#pragma unroll
            for (int mf = 0; mf < 4; mf++)
#pragma unroll
                for (int nf = 0; nf < NF; nf++)
                    mma16816(acc[mf][nf], aa[mf], &bb[nf >> 1][(nf & 1) * 2]);
        }

        if (t + 1 < T) cp_wait1(); else cp_wait0();
        __syncthreads();

        if (t + 1 < T) {
            uint32_t sn = tiles0 + ((t + 1) & 1) * STAGE;
            if (!(NT == 256 && gAw))
                tile_cp(Al, bRow, Kpad, t + 1, sn + TILE_A, tid, 4, rowIdx);
            tile_cp(Bl, bCol, Kpad, t + 1, sn + 2*TILE_A + TILE_B, tid, BTILES, nullptr);
            cp_commit();
        }

        // phase 2: Al x Bh, then Ah x Bl
#pragma unroll
        for (int ks = 0; ks < 4; ks++) {
            const uint32_t kx = (uint32_t)(ks << 5);
            uint32_t aa[4][4], bb[NB][4];
#pragma unroll
            for (int mf = 0; mf < 4; mf++) ldsm4(aa[mf], tAl + (aOff[mf] ^ kx));
#pragma unroll
            for (int nb = 0; nb < NB; nb++) ldsm4(bb[nb], tBh + (bOff[nb] ^ kx));
#pragma unroll
            for (int mf = 0; mf < 4; mf++)
#pragma unroll
                for (int nf = 0; nf < NF; nf++)
                    mma16816(acc[mf][nf], aa[mf], &bb[nf >> 1][(nf & 1) * 2]);
#pragma unroll
            for (int mf = 0; mf < 4; mf++) ldsm4(aa[mf], tAh + (aOff[mf] ^ kx));
#pragma unroll
            for (int nb = 0; nb < NB; nb++) ldsm4(bb[nb], tBl + (bOff[nb] ^ kx));
#pragma unroll
            for (int mf = 0; mf < 4; mf++)
#pragma unroll
                for (int nf = 0; nf < NF; nf++)
                    mma16816(acc[mf][nf], aa[mf], &bb[nf >> 1][(nf & 1) * 2]);
        }
    }

    if (mode == 0) {
        // ---- normal epilogue ----
#pragma unroll
        for (int mf = 0; mf < 4; mf++) {
            int r0 = bRow + wm * 64 + mf * 16 + (lane >> 2);
#pragma unroll
            for (int nf = 0; nf < NF; nf++) {
                int cloc = wn * (NT/4) + nf * 8 + (lane & 3) * 2;
                int c0 = bCol + cloc;
                float b0 = Sb[cloc], b1 = Sb[cloc + 1];
                float v0 = acc[mf][nf][0] + b0;
                float v1 = acc[mf][nf][1] + b1;
                float v2 = acc[mf][nf][2] + b0;
                float v3 = acc[mf][nf][3] + b1;
                if (doRelu) {
                    v0 = fmaxf(v0, 0.f); v1 = fmaxf(v1, 0.f);
                    v2 = fmaxf(v2, 0.f); v3 = fmaxf(v3, 0.f);
                }
                if (Cf) {
                    size_t o0 = (size_t)r0 * Kout + c0;
                    size_t o1 = (size_t)(r0 + 8) * Kout + c0;
                    *(float2*)&Cf[o0] = make_float2(v0, v1);
                    *(float2*)&Cf[o1] = make_float2(v2, v3);
                }
                if (Ch) {
                    size_t o0 = (size_t)r0 * strideC + c0;
                    size_t o1 = (size_t)(r0 + 8) * strideC + c0;
                    bf16 h0, l0, h1, l1;
                    split_bf16(v0, h0, l0); split_bf16(v1, h1, l1);
                    *(uint32_t*)&Ch[o0] = pack2(h0, h1);
                    *(uint32_t*)&Cl[o0] = pack2(l0, l1);
                    split_bf16(v2, h0, l0); split_bf16(v3, h1, l1);
                    *(uint32_t*)&Ch[o1] = pack2(h0, h1);
                    *(uint32_t*)&Cl[o1] = pack2(l0, l1);
                }
            }
        }
    } else if (NT == 256) {
        // ---- fused epilogues: stash acc+bias tile in smem ----
        __syncthreads();
        float* St  = (float*)(smem + 1024);                       // [128][RS]
        float* Xs  = (float*)(smem + 1024 + 128 * RS * 4);        // 256 (mode 2: iw3)
        float* ciw = (float*)(smem + 1024 + 128 * RS * 4 + 1024); // [4][256] (mode 1)
        float* crd = ciw + 4 * 256;                               // [128][4] (mode 1)
#pragma unroll
        for (int mf = 0; mf < 4; mf++) {
            int rl = wm * 64 + mf * 16 + (lane >> 2);
#pragma unroll
            for (int nf = 0; nf < NF; nf++) {
                int cloc = wn * (NT/4) + nf * 8 + (lane & 3) * 2;
                float b0 = Sb[cloc], b1 = Sb[cloc + 1];
                St[rl * RS + cloc]           = acc[mf][nf][0] + b0;
                St[rl * RS + cloc + 1]       = acc[mf][nf][1] + b1;
                St[(rl + 8) * RS + cloc]     = acc[mf][nf][2] + b0;
                St[(rl + 8) * RS + cloc + 1] = acc[mf][nf][3] + b1;
            }
        }
        if (mode == 2) Xs[tid] = iw3[tid];
        if (mode == 1) {
#pragma unroll
            for (int k = 0; k < 4; k++)
                ciw[k * 256 + tid] = iw1full[(768 + k) * 256 + tid];
            if (tid < 128) {
#pragma unroll
                for (int k = 0; k < 4; k++)
                    crd[tid * 4 + k] = coords[(size_t)(bRow + tid) * 5 + 1 + k];
            }
        }
        __syncthreads();

        if (mode == 1) {
#pragma unroll
            for (int rr = 0; rr < 16; rr++) {
                int r = wid * 16 + rr;
                float c0 = crd[r*4], c1 = crd[r*4+1], c2 = crd[r*4+2], c3 = crd[r*4+3];
                float vals[8];
                float s = 0.f, s2 = 0.f;
#pragma unroll
                for (int j = 0; j < 8; j++) {
                    int c = lane + j * 32;
                    float v = St[r * RS + c]
                        + c0 * ciw[c] + c1 * ciw[256 + c]
                        + c2 * ciw[512 + c] + c3 * ciw[768 + c];
                    v = fmaxf(v, 0.f);
                    vals[j] = v; s += v; s2 += v * v;
                }
#pragma unroll
                for (int off = 16; off > 0; off >>= 1) {
                    s  += __shfl_xor_sync(0xFFFFFFFFu, s,  off);
                    s2 += __shfl_xor_sync(0xFFFFFFFFu, s2, off);
                }
                float mu  = s * (1.f / IHD);
                float var = s2 * (1.f / IHD) - mu * mu;
                float inv = rsqrtf(var + 1e-5f);
                size_t base = (size_t)(bRow + r) * IHD;
#pragma unroll
                for (int j = 0; j < 8; j++) {
                    int c = lane + j * 32;
                    float v = (vals[j] - mu) * inv * ln_g[c] + ln_b[c];
                    bf16 h, l; split_bf16(v, h, l);
                    Ch[base + c] = h; Cl[base + c] = l;
                }
            }
        } else if (mode == 2) {
#pragma unroll
            for (int rr = 0; rr < 16; rr++) {
                int r = wid * 16 + rr;
                float a = 0.f;
#pragma unroll
                for (int j = 0; j < 8; j++) {
                    int c = lane + j * 32;
                    a = fmaf(fmaxf(St[r * RS + c], 0.f), Xs[c], a);
                }
#pragma unroll
                for (int off = 16; off > 0; off >>= 1)
                    a += __shfl_xor_sync(0xFFFFFFFFu, a, off);
                if (lane == 0) impOut[bRow + r] = a + ib3[0];
            }
        } else {
            // mode 3: max-pool each 16-row group, split, write pooled
#pragma unroll
            for (int gi = 0; gi < 8; gi++) {
                float m = -INFINITY;
#pragma unroll
                for (int s = 0; s < KNN; s++)
                    m = fmaxf(m, St[(gi * 16 + s) * RS + tid]);
                int grp = blockIdx.y * 8 + gi;
                bf16 h, l; split_bf16(m, h, l);
                Ch[(size_t)grp * TOKD + bCol + tid] = h;
                Cl[(size_t)grp * TOKD + bCol + tid] = l;
            }
        }
    }
}

// ---------------- fused prep megakernel ----------------
__device__ __forceinline__ void wsplit_blk(const float* __restrict__ W,
                                           bf16* __restrict__ hi, bf16* __restrict__ lo,
                                           int Kin, int Kout, int Kpad, int blk, int tid)
{
    int id = blk * 256 + tid;
    if (id >= Kout * Kpad) return;
    int n = id / Kpad, k = id - n * Kpad;
    float v = (k < Kin) ? W[(size_t)k * Kout + n] : 0.f;
    bf16 h, l; split_bf16(v, h, l);
    hi[id] = h; lo[id] = l;
}

__global__ __launch_bounds__(256) void prep_all(
    const float* __restrict__ coords, float4* __restrict__ c4,
    const float* __restrict__ w2, bf16* __restrict__ w2h, bf16* __restrict__ w2l,
    const float* __restrict__ w3, bf16* __restrict__ w3h, bf16* __restrict__ w3l,
    const float* __restrict__ w4, bf16* __restrict__ w4h, bf16* __restrict__ w4l,
    const float* __restrict__ iw2, bf16* __restrict__ iw2h, bf16* __restrict__ iw2l,
    const float* __restrict__ nw1, bf16* __restrict__ nw1h, bf16* __restrict__ nw1l,
    const float* __restrict__ nw2, bf16* __restrict__ nw2h, bf16* __restrict__ nw2l,
    const float* __restrict__ iw1, bf16* __restrict__ wih, bf16* __restrict__ wil,
    const float* __restrict__ b4, const float* __restrict__ ib1,
    float* __restrict__ b2)
{
    __shared__ float w4row[768];
    const int bid = blockIdx.x;
    const int tid = threadIdx.x;

    if (bid < 512) {
        int i = bid * 256 + tid;
        const float* p = coords + (size_t)i * 5 + 1;
        c4[i] = make_float4(p[0], p[1], p[2], p[3]);
    } else if (bid < 1024) {
        wsplit_blk(w2, w2h, w2l, 256, 512, 256, bid - 512, tid);
    } else if (bid < 2560) {
        wsplit_blk(w3, w3h, w3l, 512, 768, 512, bid - 1024, tid);
    } else if (bid < 4864) {
        wsplit_blk(w4, w4h, w4l, 768, 768, 768, bid - 2560, tid);
    } else if (bid < 5120) {
        wsplit_blk(iw2, iw2h, iw2l, 256, 256, 256, bid - 4864, tid);
    } else if (bid < 7424) {
        wsplit_blk(nw1, nw1h, nw1l, 768, 768, 768, bid - 5120, tid);
    } else if (bid < 9728) {
        wsplit_blk(nw2, nw2h, nw2l, 768, 768, 768, bid - 7424, tid);
    } else if (bid < 10496) {
        int j = bid - 9728;       // 768 rows
        for (int i = tid; i < 768; i += 256) w4row[i] = w4[j * 768 + i];
        __syncthreads();
        float s0 = 0.f, s1 = 0.f, s2 = 0.f, s3 = 0.f;
#pragma unroll 8
        for (int c = 0; c < 768; c += 4) {
            s0 = fmaf(w4row[c],     iw1[(c)     * 256 + tid], s0);
            s1 = fmaf(w4row[c + 1], iw1[(c + 1) * 256 + tid], s1);
            s2 = fmaf(w4row[c + 2], iw1[(c + 2) * 256 + tid], s2);
            s3 = fmaf(w4row[c + 3], iw1[(c + 3) * 256 + tid], s3);
        }
        float s = (s0 + s1) + (s2 + s3);
        bf16 h, l; split_bf16(s, h, l);
        wih[tid * 768 + j] = h; wil[tid * 768 + j] = l;
    } else {
        float s0 = 0.f, s1 = 0.f, s2 = 0.f, s3 = 0.f;
#pragma unroll 8
        for (int c = 0; c < 768; c += 4) {
            s0 = fmaf(b4[c],     iw1[(c)     * 256 + tid], s0);
            s1 = fmaf(b4[c + 1], iw1[(c + 1) * 256 + tid], s1);
            s2 = fmaf(b4[c + 2], iw1[(c + 2) * 256 + tid], s2);
            s3 = fmaf(b4[c + 3], iw1[(c + 3) * 256 + tid], s3);
        }
        b2[tid] = ib1[tid] + (s0 + s1) + (s2 + s3);
    }
}

// ---------------- per-batch top-128 via radix select + sort by t ----------------
__global__ __launch_bounds__(1024) void topk_kernel(
    const float* __restrict__ imp, const float* __restrict__ coords,
    const float* __restrict__ noise,
    int* __restrict__ sel_out, float* __restrict__ out_cents,
    float* __restrict__ out_masks)
{
    extern __shared__ uint32_t keys[];          // PP keys
    __shared__ uint32_t hist[256];
    __shared__ int sh_bucket, sh_target, gtCnt;
    __shared__ float selT[MT];
    __shared__ int   selI[MT];
    __shared__ int   red_i[1024];
    const int b   = blockIdx.x;
    const int tid = threadIdx.x;

    for (int i = tid; i < PP; i += 1024) {
        float v = imp[b * PP + i] + noise[b * PP + i];
        uint32_t u = __float_as_uint(v);
        keys[i] = (u & 0x80000000u) ? ~u : (u | 0x80000000u);
    }
    if (tid == 0) { sh_target = MT; gtCnt = 0; }
    __syncthreads();

    uint32_t pfx = 0, mask = 0;
#pragma unroll
    for (int B = 3; B >= 0; B--) {
        if (tid < 256) hist[tid] = 0u;
        __syncthreads();
        for (int i = tid; i < PP; i += 1024) {
            uint32_t k = keys[i];
            if ((k & mask) == pfx)
                atomicAdd(&hist[(k >> (8 * B)) & 0xFF], 1u);
        }
        __syncthreads();
        if (tid == 0) {
            int tgt = sh_target, cum = 0, bucket = 0;
            for (int v = 255; v >= 0; v--) {
                int h = (int)hist[v];
                if (cum + h >= tgt) { bucket = v; break; }
                cum += h;
            }
            sh_bucket = bucket;
            sh_target = tgt - cum;
        }
        __syncthreads();
        pfx |= ((uint32_t)sh_bucket) << (8 * B);
        mask |= 0xFFu << (8 * B);
        __syncthreads();
    }
    const uint32_t Kt = pfx;
    const int nEq = sh_target;

    for (int i = tid; i < PP; i += 1024) {
        if (keys[i] > Kt) {
            int pos = atomicAdd(&gtCnt, 1);
            selI[pos] = i;
        }
    }
    __syncthreads();
    int base = gtCnt;
    int last = -1;
    for (int r = 0; r < nEq; r++) {
        int loc = 0x7FFFFFFF;
        for (int i = tid; i < PP; i += 1024)
            if (keys[i] == Kt && i > last && i < loc) loc = i;
        red_i[tid] = loc;
        __syncthreads();
        for (int off = 512; off > 0; off >>= 1) {
            if (tid < off) red_i[tid] = min(red_i[tid], red_i[tid + off]);
            __syncthreads();
        }
        if (tid == 0) selI[base + r] = red_i[0];
        last = red_i[0];
        __syncthreads();
    }

    if (tid < MT) selT[tid] = coords[((size_t)b * PP + selI[tid]) * 5 + 4];
    __syncthreads();

    for (int kk = 2; kk <= MT; kk <<= 1) {
        for (int j = kk >> 1; j > 0; j >>= 1) {
            if (tid < MT) {
                int ixj = tid ^ j;
                if (ixj > tid) {
                    bool up = ((tid & kk) == 0);
                    float a = selT[tid], c = selT[ixj];
                    if ((a > c) == up) {
                        selT[tid] = c; selT[ixj] = a;
                        int t0 = selI[tid]; selI[tid] = selI[ixj]; selI[ixj] = t0;
                    }
                }
            }
            __syncthreads();
        }
    }

    if (tid < MT) {
        int idx = selI[tid];
        sel_out[b * MT + tid] = idx;
#pragma unroll
        for (int c = 0; c < 4; c++)
            out_cents[((size_t)b * MT + tid) * 4 + c] =
                coords[((size_t)b * PP + idx) * 5 + 1 + c];
        out_masks[b * MT + tid] = 1.0f;
    }
}

// ---------------- per-centroid 16-NN (indices only, float4 coords) ----------------
__global__ __launch_bounds__(256) void knn_kernel(
    const int* __restrict__ sel, const float4* __restrict__ c4,
    int* __restrict__ knnOut)
{
    extern __shared__ float d2[];
    __shared__ float rv[256], lminS[256];
    __shared__ int   ri[256], largS[256];
    __shared__ int   knn[KNN];
    const int g   = blockIdx.x;
    const int b   = g >> 7;
    const int tid = threadIdx.x;

    int ci = sel[g];
    float4 cc = c4[(size_t)b * PP + ci];

    {
        float bm = INFINITY; int ba = 0x7FFFFFFF;
        for (int i = tid; i < PP; i += 256) {
            float4 p = c4[(size_t)b * PP + i];
            float dx = p.x - cc.x, dy = p.y - cc.y, dz = p.z - cc.z, dt = p.w - cc.w;
            float v = dx * dx + dy * dy + dz * dz + dt * dt;
            d2[i] = v;
            if (v < bm) { bm = v; ba = i; }
        }
        lminS[tid] = bm; largS[tid] = ba;
    }
    __syncthreads();

    for (int s = 0; s < KNN; s++) {
        rv[tid] = lminS[tid]; ri[tid] = largS[tid];
        __syncthreads();
        for (int off = 128; off > 0; off >>= 1) {
            if (tid < off) {
                float ov = rv[tid + off]; int oi = ri[tid + off];
                if (ov < rv[tid] || (ov == rv[tid] && oi < ri[tid])) {
                    rv[tid] = ov; ri[tid] = oi;
                }
            }
            __syncthreads();
        }
        int win = ri[0];
        if (tid == 0) { knn[s] = win; d2[win] = INFINITY; }
        __syncthreads();
        if (tid == (win & 255)) {
            float bm = INFINITY; int ba = 0x7FFFFFFF;
            for (int i = tid; i < PP; i += 256) {
                float v = d2[i];
                if (v < bm) { bm = v; ba = i; }
            }
            lminS[tid] = bm; largS[tid] = ba;
        }
        __syncthreads();
    }

    if (tid < KNN)
        knnOut[g * KNN + tid] = b * PP + knn[tid];
}

#define NULL9 nullptr, nullptr, nullptr, nullptr, nullptr, nullptr, nullptr, nullptr
#define NULL3 nullptr, nullptr, nullptr

// ---------------- launch ----------------
extern "C" void kernel_launch(void* const* d_in, const int* in_sizes, int n_in,
                              void* d_out, int out_size)
{
    const float* coords   = (const float*)d_in[0];
    const float* feats    = (const float*)d_in[1];
    const float* w1 = (const float*)d_in[3];  const float* b1 = (const float*)d_in[4];
    const float* w2 = (const float*)d_in[5];  const float* b2in = (const float*)d_in[6];
    const float* w3 = (const float*)d_in[7];  const float* b3 = (const float*)d_in[8];
    const float* w4 = (const float*)d_in[9];  const float* b4 = (const float*)d_in[10];
    const float* iw1 = (const float*)d_in[11]; const float* ib1 = (const float*)d_in[12];
    const float* ln_g = (const float*)d_in[13]; const float* ln_b = (const float*)d_in[14];
    const float* iw2 = (const float*)d_in[15]; const float* ib2 = (const float*)d_in[16];
    const float* iw3 = (const float*)d_in[17]; const float* ib3 = (const float*)d_in[18];
    const float* nw1 = (const float*)d_in[19]; const float* nb1 = (const float*)d_in[20];
    const float* nw2 = (const float*)d_in[21]; const float* nb2 = (const float*)d_in[22];
    const float* noise = (const float*)d_in[23];

    float* out        = (float*)d_out;
    float* out_tokens = out;
    float* out_cents  = out + (size_t)NGRP * TOKD;
    float* out_masks  = out_cents + (size_t)NGRP * 4;

    bf16 *znh,*znl,*h2h,*h2l,*h3h,*h3l,*ph,*pl,*t1h,*t1l;
    bf16 *w2h,*w2l,*w3h,*w3l,*w4h,*w4l,*wih,*wil,*iw2h,*iw2l,*nw1h,*nw1l,*nw2h,*nw2l;
    float *imp,*b2;
    float4* c4;
    int *sel,*knnidx;
    cudaGetSymbolAddress((void**)&znh, g_znh);  cudaGetSymbolAddress((void**)&znl, g_znl);
    cudaGetSymbolAddress((void**)&h2h, g_h2h);  cudaGetSymbolAddress((void**)&h2l, g_h2l);
    cudaGetSymbolAddress((void**)&h3h, g_h3h);  cudaGetSymbolAddress((void**)&h3l, g_h3l);
    cudaGetSymbolAddress((void**)&ph, g_ph);    cudaGetSymbolAddress((void**)&pl, g_pl);
    cudaGetSymbolAddress((void**)&t1h, g_t1h);  cudaGetSymbolAddress((void**)&t1l, g_t1l);
    cudaGetSymbolAddress((void**)&w2h, g_w2h);  cudaGetSymbolAddress((void**)&w2l, g_w2l);
    cudaGetSymbolAddress((void**)&w3h, g_w3h);  cudaGetSymbolAddress((void**)&w3l, g_w3l);
    cudaGetSymbolAddress((void**)&w4h, g_w4h);  cudaGetSymbolAddress((void**)&w4l, g_w4l);
    cudaGetSymbolAddress((void**)&wih, g_wih);  cudaGetSymbolAddress((void**)&wil, g_wil);
    cudaGetSymbolAddress((void**)&iw2h, g_iw2h); cudaGetSymbolAddress((void**)&iw2l, g_iw2l);
    cudaGetSymbolAddress((void**)&nw1h, g_nw1h); cudaGetSymbolAddress((void**)&nw1l, g_nw1l);
    cudaGetSymbolAddress((void**)&nw2h, g_nw2h); cudaGetSymbolAddress((void**)&nw2l, g_nw2l);
    cudaGetSymbolAddress((void**)&imp, g_imp);
    cudaGetSymbolAddress((void**)&b2,  g_b2);
    cudaGetSymbolAddress((void**)&c4,  g_c4);
    cudaGetSymbolAddress((void**)&sel, g_sel);
    cudaGetSymbolAddress((void**)&knnidx, g_knn);

    cudaFuncSetAttribute(mma_gemm<256>,
        cudaFuncAttributeMaxDynamicSharedMemorySize, MMA_SMEM);
    cudaFuncSetAttribute(mma_gemm<128>,
        cudaFuncAttributeMaxDynamicSharedMemorySize, MMA_SMEM128);
    cudaFuncSetAttribute(topk_kernel,
        cudaFuncAttributeMaxDynamicSharedMemorySize, PP * sizeof(uint32_t));
    cudaFuncSetAttribute(knn_kernel,
        cudaFuncAttributeMaxDynamicSharedMemorySize, PP * sizeof(float));

    // one fused prep launch (all weight splits + wi_contract + bias2 + c4 pack)
    prep_all<<<10497, 256>>>(coords, c4,
        w2, w2h, w2l, w3, w3h, w3l, w4, w4h, w4l,
        iw2, iw2h, iw2l, nw1, nw1h, nw1l, nw2, nw2h, nw2l,
        iw1, wih, wil, b4, ib1, b2);

    // L2 GEMM with fused h1 generation (feats -> h1 -> h2)
    mma_gemm<256><<<dim3(2, NPT/128), 256, MMA_SMEM>>>(nullptr, nullptr, w2h, w2l, b2in,
        nullptr, h2h, h2l, 512, 256, 512, 1, 0, NULL9, feats, w1, b1);

    // L3 GEMM (h2 -> h3)
    mma_gemm<256><<<dim3(3, NPT/128), 256, MMA_SMEM>>>(h2h, h2l, w3h, w3l, b3,
        nullptr, h3h, h3l, 768, 512, 768, 1, 0, NULL9, NULL3);

    // importance head: h3 @ W4i + coords term, fused relu+LN+split -> zn
    mma_gemm<256><<<dim3(1, NPT/128), 256, MMA_SMEM>>>(h3h, h3l, wih, wil, b2,
        nullptr, znh, znl, 0, 768, 256, 0, 1,
        ln_g, ln_b, nullptr, nullptr, nullptr, nullptr, coords, iw1, NULL3);
    // zn @ iw2, fused relu + iw3 dot -> imp
    mma_gemm<256><<<dim3(1, NPT/128), 256, MMA_SMEM>>>(znh, znl, iw2h, iw2l, ib2,
        nullptr, nullptr, nullptr, 0, 256, 256, 0, 2,
        nullptr, nullptr, iw3, ib3, imp, nullptr, nullptr, nullptr, NULL3);

    // radix-select top-128 + sort + cents/masks
    topk_kernel<<<BSZ, 1024, PP * sizeof(uint32_t)>>>(
        imp, coords, noise, sel, out_cents, out_masks);
    // knn indices (packed coords)
    knn_kernel<<<NGRP, 256, PP * sizeof(float)>>>(sel, c4, knnidx);

    // gathered L4 over neighbor rows only, fused 16-row max-pool + split -> pooled
    mma_gemm<256><<<dim3(3, NGATH/128), 256, MMA_SMEM>>>(h3h, h3l, w4h, w4l, b4,
        nullptr, ph, pl, 0, 768, 768, 0, 3,
        nullptr, nullptr, nullptr, nullptr, nullptr, knnidx, nullptr, nullptr, NULL3);

    // token MLP (NT=128 tiles: 48 CTAs)
    mma_gemm<128><<<dim3(6, NGRP/128), 256, MMA_SMEM128>>>(ph, pl, nw1h, nw1l, nb1,
        nullptr, t1h, t1l, 768, 768, 768, 1, 0, NULL9, NULL3);
    mma_gemm<128><<<dim3(6, NGRP/128), 256, MMA_SMEM128>>>(t1h, t1l, nw2h, nw2l, nb2,
        out_tokens, nullptr, nullptr, 0, 768, 768, 0, 0, NULL9, NULL3);
}

// round 16
// speedup vs baseline: 1.3741x; 1.3741x over previous
#include <cuda_runtime.h>
#include <cuda_bf16.h>
#include <cuda_fp16.h>
#include <math.h>
#include <stdint.h>

#define BSZ 8
#define PP  16384
#define NPT (BSZ*PP)       // 131072
#define TOKD 768
#define MT  128
#define KNN 16
#define IHD 256
#define NGRP (BSZ*MT)      // 1024 centroids
#define NGATH (NGRP*KNN)   // 16384 gathered rows

typedef __half f16;

// ---------------- scratch (device globals) ----------------
__device__ f16   g_znh[(size_t)NPT*256];
__device__ f16   g_znl[(size_t)NPT*256];
__device__ f16   g_h2h[(size_t)NPT*512];
__device__ f16   g_h2l[(size_t)NPT*512];
__device__ f16   g_h3h[(size_t)NPT*768];
__device__ f16   g_h3l[(size_t)NPT*768];
__device__ float g_imp[NPT];
__device__ float4 g_c4[NPT];
__device__ int   g_sel[NGRP];
__device__ int   g_knn[NGATH];
__device__ f16   g_ph[(size_t)NGRP*768], g_pl[(size_t)NGRP*768];
__device__ f16   g_t1h[(size_t)NGRP*768], g_t1l[(size_t)NGRP*768];
// transposed fp16 weights: layout [Kout][Kpad] (single term)
__device__ f16   g_w2h[512*256];
__device__ f16   g_w3h[768*512];
__device__ f16   g_w4h[768*768];
__device__ f16   g_wih[256*768];     // W4i = w4 @ iw1[0:768]
__device__ float g_b2[256];          // ib1 + b4 @ iw1[0:768]
__device__ f16   g_iw2h[256*256];
__device__ f16   g_nw1h[768*768];
__device__ f16   g_nw2h[768*768];

// ---------------- PTX helpers (baseline ISA only) ----------------
__device__ __forceinline__ uint32_t smem_u32(const void* p) {
    uint32_t a;
    asm("{ .reg .u64 t; cvta.to.shared.u64 t, %1; cvt.u32.u64 %0, t; }"
        : "=r"(a) : "l"(p));
    return a;
}
__device__ __forceinline__ void cp16(uint32_t dst, const void* src) {
    asm volatile("cp.async.cg.shared.global [%0], [%1], 16;"
        :: "r"(dst), "l"(src) : "memory");
}
__device__ __forceinline__ void cp_commit() {
    asm volatile("cp.async.commit_group;" ::: "memory");
}
__device__ __forceinline__ void cp_wait0() {
    asm volatile("cp.async.wait_group 0;" ::: "memory");
}
__device__ __forceinline__ void ldsm4(uint32_t* r, uint32_t a) {
    asm volatile("ldmatrix.sync.aligned.m8n8.x4.shared.b16 {%0,%1,%2,%3}, [%4];"
        : "=r"(r[0]), "=r"(r[1]), "=r"(r[2]), "=r"(r[3]) : "r"(a));
}
__device__ __forceinline__ void mma16816(float* d, const uint32_t* a, const uint32_t* b) {
    asm volatile("mma.sync.aligned.m16n8k16.row.col.f32.f16.f16.f32 "
        "{%0,%1,%2,%3}, {%4,%5,%6,%7}, {%8,%9}, {%0,%1,%2,%3};"
        : "+f"(d[0]), "+f"(d[1]), "+f"(d[2]), "+f"(d[3])
        : "r"(a[0]), "r"(a[1]), "r"(a[2]), "r"(a[3]), "r"(b[0]), "r"(b[1]));
}
__device__ __forceinline__ void split_f16(float v, f16& h, f16& l) {
    h = __float2half_rn(v);
    l = __float2half_rn(v - __half2float(h));
}
__device__ __forceinline__ uint32_t pack2h(f16 a, f16 b) {
    __half2 t; t.x = a; t.y = b;
    return *(uint32_t*)&t;
}

// ---------------- mma.sync fp16 2-term GEMM, 128xNT CTA tile ----------------
#define TILE_A   16384          // 128x64 f16 tile (A hi or lo)
#define RS 264                  // stash row stride (floats)
#define STAGE256  (2*TILE_A + 256*128)          // 65536
#define EXTRA_OFF (1024 + 2*STAGE256)           // 132096
#define MMA_SMEM  143872                        // max(genA 142336, stash 143360)
#define MMA_SMEM128 (1024 + 2*(2*TILE_A + 128*128))  // 99328

extern __shared__ char smem_dyn_c[];

// cp.async one tile (nri*256 16B-chunks) with SW128 swizzle; optional row indirection
__device__ __forceinline__ void tile_cp(const f16* __restrict__ src, int rowBase,
                                        int Kstride, int kc, uint32_t dstBase,
                                        int tid, int nri, const int* __restrict__ rowIdx)
{
#pragma unroll
    for (int j = 0; j < 8; j++) {
        if (j >= nri) break;
        int i = tid + j * 256;
        int r = i >> 3, ck = i & 7;
        int gr = rowIdx ? rowIdx[rowBase + r] : (rowBase + r);
        const f16* s = src + (size_t)gr * Kstride + kc * 64 + ck * 8;
        uint32_t off = (uint32_t)(r * 128 + ((ck * 16) ^ ((r & 7) << 4)));
        cp16(dstBase + off, s);
    }
}

// generate h1 chunk (128 rows x 64 cols at kc*64) straight into smem tiles
__device__ __forceinline__ void gen_h1_tile(char* smem, char* dstAh, char* dstAl,
                                            int kc, int tid)
{
    const float* w1s = (const float*)(smem + EXTRA_OFF);
    const float* b1s = (const float*)(smem + EXTRA_OFF + 6144);
    const float* fs  = (const float*)(smem + EXTRA_OFF + 7168);
#pragma unroll
    for (int j = 0; j < 4; j++) {
        int i = tid + j * 256;
        int r = i >> 3, ck = i & 7;
        int c0 = kc * 64 + ck * 8;
        const float* fr = &fs[r * 6];
        float f0 = fr[0], f1 = fr[1], f2 = fr[2], f3 = fr[3], f4 = fr[4], f5 = fr[5];
        uint32_t hp[4], lp[4];
#pragma unroll
        for (int m = 0; m < 4; m++) {
            int ca = c0 + m * 2, cb = c0 + m * 2 + 1;
            float va = b1s[ca] + f0 * w1s[ca] + f1 * w1s[256 + ca] + f2 * w1s[512 + ca]
                     + f3 * w1s[768 + ca] + f4 * w1s[1024 + ca] + f5 * w1s[1280 + ca];
            float vb = b1s[cb] + f0 * w1s[cb] + f1 * w1s[256 + cb] + f2 * w1s[512 + cb]
                     + f3 * w1s[768 + cb] + f4 * w1s[1024 + cb] + f5 * w1s[1280 + cb];
            va = fmaxf(va, 0.f); vb = fmaxf(vb, 0.f);
            f16 ha, la, hb, lb;
            split_f16(va, ha, la); split_f16(vb, hb, lb);
            hp[m] = pack2h(ha, hb); lp[m] = pack2h(la, lb);
        }
        uint32_t off = (uint32_t)(r * 128 + ((ck * 16) ^ ((r & 7) << 4)));
        *(uint4*)(dstAh + off) = make_uint4(hp[0], hp[1], hp[2], hp[3]);
        *(uint4*)(dstAl + off) = make_uint4(lp[0], lp[1], lp[2], lp[3]);
    }
}

// mode: 0 = normal (Cf/Ch/Cl out), 1 = coords-term + relu + LN + split (Ch/Cl = zn),
//       2 = relu + dot iw3 (impOut), 3 = 16-row max-pool + split (Ch/Cl = pooled)
template<int NT>
__global__ __launch_bounds__(256)
void mma_gemm(const f16* __restrict__ Ah, const f16* __restrict__ Al,
              const f16* __restrict__ Bh,
              const float* __restrict__ bias,
              float* __restrict__ Cf, f16* __restrict__ Ch, f16* __restrict__ Cl,
              int strideC, int Kpad, int Kout, int doRelu, int mode,
              const float* __restrict__ ln_g, const float* __restrict__ ln_b,
              const float* __restrict__ iw3, const float* __restrict__ ib3,
              float* __restrict__ impOut,
              const int* __restrict__ rowIdx, const float* __restrict__ coords,
              const float* __restrict__ iw1full,
              const float* __restrict__ gAf, const float* __restrict__ gAw,
              const float* __restrict__ gAb)
{
    constexpr int TILE_B  = NT * 128;
    constexpr int STAGE   = 2*TILE_A + TILE_B;
    constexpr int NB      = NT / 64;
    constexpr int NF      = NT / 32;
    constexpr int BTILES  = NT / 32;

    char* smem = smem_dyn_c;
    const uint32_t sbase = smem_u32(smem);
    float* Sb = (float*)smem;
    const uint32_t tiles0 = sbase + 1024;
    char* tiles0p = smem + 1024;
    const int tid  = threadIdx.x;
    const int wid  = tid >> 5;
    const int lane = tid & 31;
    const int wm   = wid >> 2;
    const int wn   = wid & 3;
    const int bRow = blockIdx.y * 128;
    const int bCol = blockIdx.x * NT;

    if (tid < NT) Sb[tid] = bias[bCol + tid];

    if (NT == 256 && gAw) {
        float* w1s = (float*)(smem + EXTRA_OFF);
        float* b1s = (float*)(smem + EXTRA_OFF + 6144);
        float* fs  = (float*)(smem + EXTRA_OFF + 7168);
        for (int i = tid; i < 1536; i += 256) w1s[i] = gAw[i];
        b1s[tid] = gAb[tid];
        for (int i = tid; i < 768; i += 256) {
            int r = i / 6, k = i - r * 6;
            fs[i] = gAf[(size_t)(bRow + r) * 6 + k];
        }
        __syncthreads();
    }

    uint32_t aOff[4], bOff[NB];
    {
        int khalfA = ((lane >> 4) & 1) * 16;
#pragma unroll
        for (int mf = 0; mf < 4; mf++) {
            int r = wm * 64 + mf * 16 + ((lane >> 3) & 1) * 8 + (lane & 7);
            aOff[mf] = (uint32_t)(r * 128 + (khalfA ^ ((r & 7) << 4)));
        }
        int khalfB = ((lane >> 3) & 1) * 16;
#pragma unroll
        for (int nb = 0; nb < NB; nb++) {
            int r = wn * (NT/4) + nb * 16 + ((lane >> 4) & 1) * 8 + (lane & 7);
            bOff[nb] = (uint32_t)(r * 128 + (khalfB ^ ((r & 7) << 4)));
        }
    }

    float acc[4][NF][4];
#pragma unroll
    for (int i = 0; i < 4; i++)
#pragma unroll
        for (int j = 0; j < NF; j++)
#pragma unroll
            for (int c = 0; c < 4; c++) acc[i][j][c] = 0.f;

    const int T = Kpad / 64;

    // prologue: chunk 0 -> buffer 0 (Ah, Al, Bh)
    if (NT == 256 && gAw) {
        gen_h1_tile(smem, tiles0p, tiles0p + TILE_A, 0, tid);
    } else {
        tile_cp(Ah, bRow, Kpad, 0, tiles0,            tid, 4, rowIdx);
        tile_cp(Al, bRow, Kpad, 0, tiles0 + TILE_A,   tid, 4, rowIdx);
    }
    tile_cp(Bh, bCol, Kpad, 0, tiles0 + 2*TILE_A, tid, BTILES, nullptr);
    cp_commit();

    // single-sync pipelined mainloop (R14 schedule)
    for (int t = 0; t < T; t++) {
        cp_wait0();
        __syncthreads();
        if (t + 1 < T) {
            uint32_t st = tiles0 + ((t + 1) & 1) * STAGE;
            char*    sp = tiles0p + ((t + 1) & 1) * STAGE;
            if (NT == 256 && gAw) {
                gen_h1_tile(smem, sp, sp + TILE_A, t + 1, tid);
            } else {
                tile_cp(Ah, bRow, Kpad, t + 1, st,            tid, 4, rowIdx);
                tile_cp(Al, bRow, Kpad, t + 1, st + TILE_A,   tid, 4, rowIdx);
            }
            tile_cp(Bh, bCol, Kpad, t + 1, st + 2*TILE_A, tid, BTILES, nullptr);
            cp_commit();
        }

        const uint32_t st  = tiles0 + (t & 1) * STAGE;
        const uint32_t tAh = st, tAl = st + TILE_A;
        const uint32_t tBh = st + 2*TILE_A;

#pragma unroll
        for (int ks = 0; ks < 4; ks++) {
            const uint32_t kx = (uint32_t)(ks << 5);
            uint32_t ah[4][4], al[4][4], bb[NB][4];
#pragma unroll
            for (int mf = 0; mf < 4; mf++) ldsm4(ah[mf], tAh + (aOff[mf] ^ kx));
#pragma unroll
            for (int mf = 0; mf < 4; mf++) ldsm4(al[mf], tAl + (aOff[mf] ^ kx));
#pragma unroll
            for (int nb = 0; nb < NB; nb++) ldsm4(bb[nb], tBh + (bOff[nb] ^ kx));
#pragma unroll
            for (int mf = 0; mf < 4; mf++)
#pragma unroll
                for (int nf = 0; nf < NF; nf++)
                    mma16816(acc[mf][nf], ah[mf], &bb[nf >> 1][(nf & 1) * 2]);
#pragma unroll
            for (int mf = 0; mf < 4; mf++)
#pragma unroll
                for (int nf = 0; nf < NF; nf++)
                    mma16816(acc[mf][nf], al[mf], &bb[nf >> 1][(nf & 1) * 2]);
        }
    }

    if (mode == 0) {
        // ---- normal epilogue ----
#pragma unroll
        for (int mf = 0; mf < 4; mf++) {
            int r0 = bRow + wm * 64 + mf * 16 + (lane >> 2);
#pragma unroll
            for (int nf = 0; nf < NF; nf++) {
                int cloc = wn * (NT/4) + nf * 8 + (lane & 3) * 2;
                int c0 = bCol + cloc;
                float b0 = Sb[cloc], b1 = Sb[cloc + 1];
                float v0 = acc[mf][nf][0] + b0;
                float v1 = acc[mf][nf][1] + b1;
                float v2 = acc[mf][nf][2] + b0;
                float v3 = acc[mf][nf][3] + b1;
                if (doRelu) {
                    v0 = fmaxf(v0, 0.f); v1 = fmaxf(v1, 0.f);
                    v2 = fmaxf(v2, 0.f); v3 = fmaxf(v3, 0.f);
                }
                if (Cf) {
                    size_t o0 = (size_t)r0 * Kout + c0;
                    size_t o1 = (size_t)(r0 + 8) * Kout + c0;
                    *(float2*)&Cf[o0] = make_float2(v0, v1);
                    *(float2*)&Cf[o1] = make_float2(v2, v3);
                }
                if (Ch) {
                    size_t o0 = (size_t)r0 * strideC + c0;
                    size_t o1 = (size_t)(r0 + 8) * strideC + c0;
                    f16 h0, l0, h1, l1;
                    split_f16(v0, h0, l0); split_f16(v1, h1, l1);
                    *(uint32_t*)&Ch[o0] = pack2h(h0, h1);
                    *(uint32_t*)&Cl[o0] = pack2h(l0, l1);
                    split_f16(v2, h0, l0); split_f16(v3, h1, l1);
                    *(uint32_t*)&Ch[o1] = pack2h(h0, h1);
                    *(uint32_t*)&Cl[o1] = pack2h(l0, l1);
                }
            }
        }
    } else if (NT == 256) {
        // ---- fused epilogues: stash acc+bias tile in smem ----
        __syncthreads();
        float* St  = (float*)(smem + 1024);                       // [128][RS]
        float* Xs  = (float*)(smem + 1024 + 128 * RS * 4);        // 256 (mode 2: iw3)
        float* ciw = (float*)(smem + 1024 + 128 * RS * 4 + 1024); // [4][256] (mode 1)
        float* crd = ciw + 4 * 256;                               // [128][4] (mode 1)
#pragma unroll
        for (int mf = 0; mf < 4; mf++) {
            int rl = wm * 64 + mf * 16 + (lane >> 2);
#pragma unroll
            for (int nf = 0; nf < NF; nf++) {
                int cloc = wn * (NT/4) + nf * 8 + (lane & 3) * 2;
                float b0 = Sb[cloc], b1 = Sb[cloc + 1];
                St[rl * RS + cloc]           = acc[mf][nf][0] + b0;
                St[rl * RS + cloc + 1]       = acc[mf][nf][1] + b1;
                St[(rl + 8) * RS + cloc]     = acc[mf][nf][2] + b0;
                St[(rl + 8) * RS + cloc + 1] = acc[mf][nf][3] + b1;
            }
        }
        if (mode == 2) Xs[tid] = iw3[tid];
        if (mode == 1) {
#pragma unroll
            for (int k = 0; k < 4; k++)
                ciw[k * 256 + tid] = iw1full[(768 + k) * 256 + tid];
            if (tid < 128) {
#pragma unroll
                for (int k = 0; k < 4; k++)
                    crd[tid * 4 + k] = coords[(size_t)(bRow + tid) * 5 + 1 + k];
            }
        }
        __syncthreads();

        if (mode == 1) {
#pragma unroll
            for (int rr = 0; rr < 16; rr++) {
                int r = wid * 16 + rr;
                float c0 = crd[r*4], c1 = crd[r*4+1], c2 = crd[r*4+2], c3 = crd[r*4+3];
                float vals[8];
                float s = 0.f, s2 = 0.f;
#pragma unroll
                for (int j = 0; j < 8; j++) {
                    int c = lane + j * 32;
                    float v = St[r * RS + c]
                        + c0 * ciw[c] + c1 * ciw[256 + c]
                        + c2 * ciw[512 + c] + c3 * ciw[768 + c];
                    v = fmaxf(v, 0.f);
                    vals[j] = v; s += v; s2 += v * v;
                }
#pragma unroll
                for (int off = 16; off > 0; off >>= 1) {
                    s  += __shfl_xor_sync(0xFFFFFFFFu, s,  off);
                    s2 += __shfl_xor_sync(0xFFFFFFFFu, s2, off);
                }
                float mu  = s * (1.f / IHD);
                float var = s2 * (1.f / IHD) - mu * mu;
                float inv = rsqrtf(var + 1e-5f);
                size_t base = (size_t)(bRow + r) * IHD;
#pragma unroll
                for (int j = 0; j < 8; j++) {
                    int c = lane + j * 32;
                    float v = (vals[j] - mu) * inv * ln_g[c] + ln_b[c];
                    f16 h, l; split_f16(v, h, l);
                    Ch[base + c] = h; Cl[base + c] = l;
                }
            }
        } else if (mode == 2) {
#pragma unroll
            for (int rr = 0; rr < 16; rr++) {
                int r = wid * 16 + rr;
                float a = 0.f;
#pragma unroll
                for (int j = 0; j < 8; j++) {
                    int c = lane + j * 32;
                    a = fmaf(fmaxf(St[r * RS + c], 0.f), Xs[c], a);
                }
#pragma unroll
                for (int off = 16; off > 0; off >>= 1)
                    a += __shfl_xor_sync(0xFFFFFFFFu, a, off);
                if (lane == 0) impOut[bRow + r] = a + ib3[0];
            }
        } else {
            // mode 3: max-pool each 16-row group, split, write pooled
#pragma unroll
            for (int gi = 0; gi < 8; gi++) {
                float m = -INFINITY;
#pragma unroll
                for (int s = 0; s < KNN; s++)
                    m = fmaxf(m, St[(gi * 16 + s) * RS + tid]);
                int grp = blockIdx.y * 8 + gi;
                f16 h, l; split_f16(m, h, l);
                Ch[(size_t)grp * TOKD + bCol + tid] = h;
                Cl[(size_t)grp * TOKD + bCol + tid] = l;
            }
        }
    }
}

// ---------------- fused prep megakernel ----------------
__device__ __forceinline__ void wsplit_blk(const float* __restrict__ W,
                                           f16* __restrict__ hi,
                                           int Kin, int Kout, int Kpad, int blk, int tid)
{
    int id = blk * 256 + tid;
    if (id >= Kout * Kpad) return;
    int n = id / Kpad, k = id - n * Kpad;
    float v = (k < Kin) ? W[(size_t)k * Kout + n] : 0.f;
    hi[id] = __float2half_rn(v);
}

__global__ __launch_bounds__(256) void prep_all(
    const float* __restrict__ coords, float4* __restrict__ c4,
    const float* __restrict__ w2, f16* __restrict__ w2h,
    const float* __restrict__ w3, f16* __restrict__ w3h,
    const float* __restrict__ w4, f16* __restrict__ w4h,
    const float* __restrict__ iw2, f16* __restrict__ iw2h,
    const float* __restrict__ nw1, f16* __restrict__ nw1h,
    const float* __restrict__ nw2, f16* __restrict__ nw2h,
    const float* __restrict__ iw1, f16* __restrict__ wih,
    const float* __restrict__ b4, const float* __restrict__ ib1,
    float* __restrict__ b2)
{
    __shared__ float w4row[768];
    const int bid = blockIdx.x;
    const int tid = threadIdx.x;

    if (bid < 512) {
        int i = bid * 256 + tid;
        const float* p = coords + (size_t)i * 5 + 1;
        c4[i] = make_float4(p[0], p[1], p[2], p[3]);
    } else if (bid < 1024) {
        wsplit_blk(w2, w2h, 256, 512, 256, bid - 512, tid);
    } else if (bid < 2560) {
        wsplit_blk(w3, w3h, 512, 768, 512, bid - 1024, tid);
    } else if (bid < 4864) {
        wsplit_blk(w4, w4h, 768, 768, 768, bid - 2560, tid);
    } else if (bid < 5120) {
        wsplit_blk(iw2, iw2h, 256, 256, 256, bid - 4864, tid);
    } else if (bid < 7424) {
        wsplit_blk(nw1, nw1h, 768, 768, 768, bid - 5120, tid);
    } else if (bid < 9728) {
        wsplit_blk(nw2, nw2h, 768, 768, 768, bid - 7424, tid);
    } else if (bid < 10496) {
        int j = bid - 9728;       // 768 rows
        for (int i = tid; i < 768; i += 256) w4row[i] = w4[j * 768 + i];
        __syncthreads();
        float s0 = 0.f, s1 = 0.f, s2 = 0.f, s3 = 0.f;
#pragma unroll 8
        for (int c = 0; c < 768; c += 4) {
            s0 = fmaf(w4row[c],     iw1[(c)     * 256 + tid], s0);
            s1 = fmaf(w4row[c + 1], iw1[(c + 1) * 256 + tid], s1);
            s2 = fmaf(w4row[c + 2], iw1[(c + 2) * 256 + tid], s2);
            s3 = fmaf(w4row[c + 3], iw1[(c + 3) * 256 + tid], s3);
        }
        float s = (s0 + s1) + (s2 + s3);
        wih[tid * 768 + j] = __float2half_rn(s);
    } else {
        float s0 = 0.f, s1 = 0.f, s2 = 0.f, s3 = 0.f;
#pragma unroll 8
        for (int c = 0; c < 768; c += 4) {
            s0 = fmaf(b4[c],     iw1[(c)     * 256 + tid], s0);
            s1 = fmaf(b4[c + 1], iw1[(c + 1) * 256 + tid], s1);
            s2 = fmaf(b4[c + 2], iw1[(c + 2) * 256 + tid], s2);
            s3 = fmaf(b4[c + 3], iw1[(c + 3) * 256 + tid], s3);
        }
        b2[tid] = ib1[tid] + (s0 + s1) + (s2 + s3);
    }
}

// ---------------- per-batch top-128 via radix select + sort by t ----------------
__global__ __launch_bounds__(1024) void topk_kernel(
    const float* __restrict__ imp, const float* __restrict__ coords,
    const float* __restrict__ noise,
    int* __restrict__ sel_out, float* __restrict__ out_cents,
    float* __restrict__ out_masks)
{
    extern __shared__ uint32_t keys[];          // PP keys
    __shared__ uint32_t hist[256];
    __shared__ int sh_bucket, sh_target, gtCnt;
    __shared__ float selT[MT];
    __shared__ int   selI[MT];
    __shared__ int   red_i[1024];
    const int b   = blockIdx.x;
    const int tid = threadIdx.x;

    for (int i = tid; i < PP; i += 1024) {
        float v = imp[b * PP + i] + noise[b * PP + i];
        uint32_t u = __float_as_uint(v);
        keys[i] = (u & 0x80000000u) ? ~u : (u | 0x80000000u);
    }
    if (tid == 0) { sh_target = MT; gtCnt = 0; }
    __syncthreads();

    uint32_t pfx = 0, mask = 0;
#pragma unroll
    for (int B = 3; B >= 0; B--) {
        if (tid < 256) hist[tid] = 0u;
        __syncthreads();
        for (int i = tid; i < PP; i += 1024) {
            uint32_t k = keys[i];
            if ((k & mask) == pfx)
                atomicAdd(&hist[(k >> (8 * B)) & 0xFF], 1u);
        }
        __syncthreads();
        if (tid == 0) {
            int tgt = sh_target, cum = 0, bucket = 0;
            for (int v = 255; v >= 0; v--) {
                int h = (int)hist[v];
                if (cum + h >= tgt) { bucket = v; break; }
                cum += h;
            }
            sh_bucket = bucket;
            sh_target = tgt - cum;
        }
        __syncthreads();
        pfx |= ((uint32_t)sh_bucket) << (8 * B);
        mask |= 0xFFu << (8 * B);
        __syncthreads();
    }
    const uint32_t Kt = pfx;
    const int nEq = sh_target;

    for (int i = tid; i < PP; i += 1024) {
        if (keys[i] > Kt) {
            int pos = atomicAdd(&gtCnt, 1);
            selI[pos] = i;
        }
    }
    __syncthreads();
    int base = gtCnt;
    int last = -1;
    for (int r = 0; r < nEq; r++) {
        int loc = 0x7FFFFFFF;
        for (int i = tid; i < PP; i += 1024)
            if (keys[i] == Kt && i > last && i < loc) loc = i;
        red_i[tid] = loc;
        __syncthreads();
        for (int off = 512; off > 0; off >>= 1) {
            if (tid < off) red_i[tid] = min(red_i[tid], red_i[tid + off]);
            __syncthreads();
        }
        if (tid == 0) selI[base + r] = red_i[0];
        last = red_i[0];
        __syncthreads();
    }

    if (tid < MT) selT[tid] = coords[((size_t)b * PP + selI[tid]) * 5 + 4];
    __syncthreads();

    for (int kk = 2; kk <= MT; kk <<= 1) {
        for (int j = kk >> 1; j > 0; j >>= 1) {
            if (tid < MT) {
                int ixj = tid ^ j;
                if (ixj > tid) {
                    bool up = ((tid & kk) == 0);
                    float a = selT[tid], c = selT[ixj];
                    if ((a > c) == up) {
                        selT[tid] = c; selT[ixj] = a;
                        int t0 = selI[tid]; selI[tid] = selI[ixj]; selI[ixj] = t0;
                    }
                }
            }
            __syncthreads();
        }
    }

    if (tid < MT) {
        int idx = selI[tid];
        sel_out[b * MT + tid] = idx;
#pragma unroll
        for (int c = 0; c < 4; c++)
            out_cents[((size_t)b * MT + tid) * 4 + c] =
                coords[((size_t)b * PP + idx) * 5 + 1 + c];
        out_masks[b * MT + tid] = 1.0f;
    }
}

// ---------------- per-centroid 16-NN (indices only, float4 coords) ----------------
__global__ __launch_bounds__(256) void knn_kernel(
    const int* __restrict__ sel, const float4* __restrict__ c4,
    int* __restrict__ knnOut)
{
    extern __shared__ float d2[];
    __shared__ float rv[256], lminS[256];
    __shared__ int   ri[256], largS[256];
    __shared__ int   knn[KNN];
    const int g   = blockIdx.x;
    const int b   = g >> 7;
    const int tid = threadIdx.x;

    int ci = sel[g];
    float4 cc = c4[(size_t)b * PP + ci];

    {
        float bm = INFINITY; int ba = 0x7FFFFFFF;
        for (int i = tid; i < PP; i += 256) {
            float4 p = c4[(size_t)b * PP + i];
            float dx = p.x - cc.x, dy = p.y - cc.y, dz = p.z - cc.z, dt = p.w - cc.w;
            float v = dx * dx + dy * dy + dz * dz + dt * dt;
            d2[i] = v;
            if (v < bm) { bm = v; ba = i; }
        }
        lminS[tid] = bm; largS[tid] = ba;
    }
    __syncthreads();

    for (int s = 0; s < KNN; s++) {
        rv[tid] = lminS[tid]; ri[tid] = largS[tid];
        __syncthreads();
        for (int off = 128; off > 0; off >>= 1) {
            if (tid < off) {
                float ov = rv[tid + off]; int oi = ri[tid + off];
                if (ov < rv[tid] || (ov == rv[tid] && oi < ri[tid])) {
                    rv[tid] = ov; ri[tid] = oi;
                }
            }
            __syncthreads();
        }
        int win = ri[0];
        if (tid == 0) { knn[s] = win; d2[win] = INFINITY; }
        __syncthreads();
        if (tid == (win & 255)) {
            float bm = INFINITY; int ba = 0x7FFFFFFF;
            for (int i = tid; i < PP; i += 256) {
                float v = d2[i];
                if (v < bm) { bm = v; ba = i; }
            }
            lminS[tid] = bm; largS[tid] = ba;
        }
        __syncthreads();
    }

    if (tid < KNN)
        knnOut[g * KNN + tid] = b * PP + knn[tid];
}

#define NULL9 nullptr, nullptr, nullptr, nullptr, nullptr, nullptr, nullptr, nullptr
#define NULL3 nullptr, nullptr, nullptr

// ---------------- launch ----------------
extern "C" void kernel_launch(void* const* d_in, const int* in_sizes, int n_in,
                              void* d_out, int out_size)
{
    const float* coords   = (const float*)d_in[0];
    const float* feats    = (const float*)d_in[1];
    const float* w1 = (const float*)d_in[3];  const float* b1 = (const float*)d_in[4];
    const float* w2 = (const float*)d_in[5];  const float* b2in = (const float*)d_in[6];
    const float* w3 = (const float*)d_in[7];  const float* b3 = (const float*)d_in[8];
    const float* w4 = (const float*)d_in[9];  const float* b4 = (const float*)d_in[10];
    const float* iw1 = (const float*)d_in[11]; const float* ib1 = (const float*)d_in[12];
    const float* ln_g = (const float*)d_in[13]; const float* ln_b = (const float*)d_in[14];
    const float* iw2 = (const float*)d_in[15]; const float* ib2 = (const float*)d_in[16];
    const float* iw3 = (const float*)d_in[17]; const float* ib3 = (const float*)d_in[18];
    const float* nw1 = (const float*)d_in[19]; const float* nb1 = (const float*)d_in[20];
    const float* nw2 = (const float*)d_in[21]; const float* nb2 = (const float*)d_in[22];
    const float* noise = (const float*)d_in[23];

    float* out        = (float*)d_out;
    float* out_tokens = out;
    float* out_cents  = out + (size_t)NGRP * TOKD;
    float* out_masks  = out_cents + (size_t)NGRP * 4;

    f16 *znh,*znl,*h2h,*h2l,*h3h,*h3l,*ph,*pl,*t1h,*t1l;
    f16 *w2h,*w3h,*w4h,*wih,*iw2h,*nw1h,*nw2h;
    float *imp,*b2;
    float4* c4;
    int *sel,*knnidx;
    cudaGetSymbolAddress((void**)&znh, g_znh);  cudaGetSymbolAddress((void**)&znl, g_znl);
    cudaGetSymbolAddress((void**)&h2h, g_h2h);  cudaGetSymbolAddress((void**)&h2l, g_h2l);
    cudaGetSymbolAddress((void**)&h3h, g_h3h);  cudaGetSymbolAddress((void**)&h3l, g_h3l);
    cudaGetSymbolAddress((void**)&ph, g_ph);    cudaGetSymbolAddress((void**)&pl, g_pl);
    cudaGetSymbolAddress((void**)&t1h, g_t1h);  cudaGetSymbolAddress((void**)&t1l, g_t1l);
    cudaGetSymbolAddress((void**)&w2h, g_w2h);
    cudaGetSymbolAddress((void**)&w3h, g_w3h);
    cudaGetSymbolAddress((void**)&w4h, g_w4h);
    cudaGetSymbolAddress((void**)&wih, g_wih);
    cudaGetSymbolAddress((void**)&iw2h, g_iw2h);
    cudaGetSymbolAddress((void**)&nw1h, g_nw1h);
    cudaGetSymbolAddress((void**)&nw2h, g_nw2h);
    cudaGetSymbolAddress((void**)&imp, g_imp);
    cudaGetSymbolAddress((void**)&b2,  g_b2);
    cudaGetSymbolAddress((void**)&c4,  g_c4);
    cudaGetSymbolAddress((void**)&sel, g_sel);
    cudaGetSymbolAddress((void**)&knnidx, g_knn);

    cudaFuncSetAttribute(mma_gemm<256>,
        cudaFuncAttributeMaxDynamicSharedMemorySize, MMA_SMEM);
    cudaFuncSetAttribute(mma_gemm<128>,
        cudaFuncAttributeMaxDynamicSharedMemorySize, MMA_SMEM128);
    cudaFuncSetAttribute(topk_kernel,
        cudaFuncAttributeMaxDynamicSharedMemorySize, PP * sizeof(uint32_t));
    cudaFuncSetAttribute(knn_kernel,
        cudaFuncAttributeMaxDynamicSharedMemorySize, PP * sizeof(float));

    // one fused prep launch (all weight converts + wi_contract + bias2 + c4 pack)
    prep_all<<<10497, 256>>>(coords, c4,
        w2, w2h, w3, w3h, w4, w4h,
        iw2, iw2h, nw1, nw1h, nw2, nw2h,
        iw1, wih, b4, ib1, b2);

    // L2 GEMM with fused h1 generation (feats -> h1 -> h2)
    mma_gemm<256><<<dim3(2, NPT/128), 256, MMA_SMEM>>>(nullptr, nullptr, w2h, b2in,
        nullptr, h2h, h2l, 512, 256, 512, 1, 0, NULL9, feats, w1, b1);

    // L3 GEMM (h2 -> h3)
    mma_gemm<256><<<dim3(3, NPT/128), 256, MMA_SMEM>>>(h2h, h2l, w3h, b3,
        nullptr, h3h, h3l, 768, 512, 768, 1, 0, NULL9, NULL3);

    // importance head: h3 @ W4i + coords term, fused relu+LN+split -> zn
    mma_gemm<256><<<dim3(1, NPT/128), 256, MMA_SMEM>>>(h3h, h3l, wih, b2,
        nullptr, znh, znl, 0, 768, 256, 0, 1,
        ln_g, ln_b, nullptr, nullptr, nullptr, nullptr, coords, iw1, NULL3);
    // zn @ iw2, fused relu + iw3 dot -> imp
    mma_gemm<256><<<dim3(1, NPT/128), 256, MMA_SMEM>>>(znh, znl, iw2h, ib2,
        nullptr, nullptr, nullptr, 0, 256, 256, 0, 2,
        nullptr, nullptr, iw3, ib3, imp, nullptr, nullptr, nullptr, NULL3);

    // radix-select top-128 + sort + cents/masks
    topk_kernel<<<BSZ, 1024, PP * sizeof(uint32_t)>>>(
        imp, coords, noise, sel, out_cents, out_masks);
    // knn indices (packed coords)
    knn_kernel<<<NGRP, 256, PP * sizeof(float)>>>(sel, c4, knnidx);

    // gathered L4 over neighbor rows only, fused 16-row max-pool + split -> pooled
    mma_gemm<256><<<dim3(3, NGATH/128), 256, MMA_SMEM>>>(h3h, h3l, w4h, b4,
        nullptr, ph, pl, 0, 768, 768, 0, 3,
        nullptr, nullptr, nullptr, nullptr, nullptr, knnidx, nullptr, nullptr, NULL3);

    // token MLP (NT=128 tiles: 48 CTAs)
    mma_gemm<128><<<dim3(6, NGRP/128), 256, MMA_SMEM128>>>(ph, pl, nw1h, nb1,
        nullptr, t1h, t1l, 768, 768, 768, 1, 0, NULL9, NULL3);
    mma_gemm<128><<<dim3(6, NGRP/128), 256, MMA_SMEM128>>>(t1h, t1l, nw2h, nb2,
        out_tokens, nullptr, nullptr, 0, 768, 768, 0, 0, NULL9, NULL3);
}